// round 5
// baseline (speedup 1.0000x reference)
#include <cuda_runtime.h>
#include <cstdint>
#include <math.h>

#define B_TOT 512
#define SEQ   392
#define CH    128
#define NHEAD 4
#define HD    32
#define NWIN  128
#define MROWS (B_TOT*SEQ)          // 200704
#define NN    (SEQ*SEQ)            // 153664
#define QKV_SCALE 0.17677669529663687f

#define KVSTR 36                   // smem row stride -> conflict-free fragments
#define NT    49                   // 392/8 n-tiles
#define MT    25                   // ceil(392/16) m-tiles

// -------- scratch (device globals: no allocations allowed) --------
__device__ float g_q[(size_t)B_TOT*NHEAD*SEQ*HD];
__device__ float g_k[(size_t)B_TOT*NHEAD*SEQ*HD];
__device__ float g_v[(size_t)B_TOT*NHEAD*SEQ*HD];
__device__ float g_ao[(size_t)MROWS*CH];
__device__ float g_bias[(size_t)NHEAD*NN];    // [h][row_q][col_k]
__device__ int   g_mflag[NWIN];

// ============================================================
__device__ __forceinline__ uint32_t f2tf32(float x) {
    uint32_t r;
    asm("cvt.rna.tf32.f32 %0, %1;" : "=r"(r) : "f"(x));
    return r;
}
__device__ __forceinline__ void mma_tf32(float& d0, float& d1, float& d2, float& d3,
                                         uint32_t a0, uint32_t a1, uint32_t a2, uint32_t a3,
                                         uint32_t b0, uint32_t b1) {
    asm volatile("mma.sync.aligned.m16n8k8.row.col.f32.tf32.tf32.f32 "
                 "{%0,%1,%2,%3}, {%4,%5,%6,%7}, {%8,%9}, {%0,%1,%2,%3};"
                 : "+f"(d0), "+f"(d1), "+f"(d2), "+f"(d3)
                 : "r"(a0), "r"(a1), "r"(a2), "r"(a3), "r"(b0), "r"(b1));
}

// ============================================================
// Prep: bias[h][n][m] = table[ridx[n][m]][h]
// ============================================================
__global__ void bias_gather_kernel(const float* __restrict__ table,
                                   const int* __restrict__ ridx) {
    int t = blockIdx.x * 256 + threadIdx.x;
    if (t >= NN) return;
    int r = ridx[t];
    float4 tv = *(const float4*)(table + (size_t)r * 4);
    g_bias[0 * (size_t)NN + t] = tv.x;
    g_bias[1 * (size_t)NN + t] = tv.y;
    g_bias[2 * (size_t)NN + t] = tv.z;
    g_bias[3 * (size_t)NN + t] = tv.w;
}

// ============================================================
// Prep: per-window "mask is nonzero" flag
// ============================================================
__global__ void maskflag_kernel(const float* __restrict__ mask) {
    int w = blockIdx.x;
    const float* mp = mask + (size_t)w * NN;
    int any = 0;
    for (int i = threadIdx.x; i < NN; i += 256)
        any |= (mp[i] != 0.0f);
    any = __syncthreads_or(any);
    if (threadIdx.x == 0) g_mflag[w] = any;
}

// ============================================================
// tf32 tensor-core GEMM: Y[M,N] = X[M,128] @ W[N,128]^T
// CTA 64x64, 8 warps (4x2), warp tile 16x32, double-buffered smem.
// ============================================================
template <int MODE>
__global__ void __launch_bounds__(256) gemm_tc(const float* __restrict__ Xin,
                                               const float* __restrict__ W,
                                               const float* __restrict__ bias,
                                               float* __restrict__ out) {
    __shared__ float Xs[2][64 * KVSTR];
    __shared__ float Ws[2][64 * KVSTR];
    const float* X = (MODE == 0) ? Xin : g_ao;

    int m0 = blockIdx.x * 64;
    int n0 = blockIdx.y * 64;
    int tid = threadIdx.x;
    int lane = tid & 31, warp = tid >> 5;
    int wm = warp >> 1, wn = warp & 1;
    int grp = lane >> 2, q4 = lane & 3;

    int lrow0 = tid >> 3, lcol = tid & 7;     // it=0 position
    int lrow1 = lrow0 + 32;                   // it=1 position

    float acc[4][4] = {};
    uint4 xr[2], wr[2];

    // ---- load chunk 0 ----
#pragma unroll
    for (int it = 0; it < 2; it++) {
        int row = (it == 0) ? lrow0 : lrow1;
        float4 xv = *(const float4*)(X + (size_t)(m0 + row) * CH + lcol * 4);
        float4 wv = *(const float4*)(W + (size_t)(n0 + row) * CH + lcol * 4);
        xr[it] = make_uint4(f2tf32(xv.x), f2tf32(xv.y), f2tf32(xv.z), f2tf32(xv.w));
        wr[it] = make_uint4(f2tf32(wv.x), f2tf32(wv.y), f2tf32(wv.z), f2tf32(wv.w));
    }
#pragma unroll
    for (int it = 0; it < 2; it++) {
        int row = (it == 0) ? lrow0 : lrow1;
        *(uint4*)(Xs[0] + row * KVSTR + lcol * 4) = xr[it];
        *(uint4*)(Ws[0] + row * KVSTR + lcol * 4) = wr[it];
    }
    __syncthreads();

#pragma unroll
    for (int kc = 0; kc < 4; kc++) {
        int cur = kc & 1;
        // prefetch next chunk
        if (kc < 3) {
            int k0 = (kc + 1) * 32;
#pragma unroll
            for (int it = 0; it < 2; it++) {
                int row = (it == 0) ? lrow0 : lrow1;
                float4 xv = *(const float4*)(X + (size_t)(m0 + row) * CH + k0 + lcol * 4);
                float4 wv = *(const float4*)(W + (size_t)(n0 + row) * CH + k0 + lcol * 4);
                xr[it] = make_uint4(f2tf32(xv.x), f2tf32(xv.y), f2tf32(xv.z), f2tf32(xv.w));
                wr[it] = make_uint4(f2tf32(wv.x), f2tf32(wv.y), f2tf32(wv.z), f2tf32(wv.w));
            }
        }
        // compute on current stage
#pragma unroll
        for (int ks = 0; ks < 4; ks++) {
            const uint32_t* xp0 = (const uint32_t*)(Xs[cur] + (wm * 16 + grp) * KVSTR + ks * 8 + q4);
            const uint32_t* xp1 = (const uint32_t*)(Xs[cur] + (wm * 16 + grp + 8) * KVSTR + ks * 8 + q4);
            uint32_t a0 = xp0[0], a1 = xp1[0], a2 = xp0[4], a3 = xp1[4];
#pragma unroll
            for (int j = 0; j < 4; j++) {
                const uint32_t* wp = (const uint32_t*)(Ws[cur] + (wn * 32 + j * 8 + grp) * KVSTR + ks * 8 + q4);
                mma_tf32(acc[j][0], acc[j][1], acc[j][2], acc[j][3],
                         a0, a1, a2, a3, wp[0], wp[4]);
            }
        }
        // store next stage
        if (kc < 3) {
            int nxt = cur ^ 1;
#pragma unroll
            for (int it = 0; it < 2; it++) {
                int row = (it == 0) ? lrow0 : lrow1;
                *(uint4*)(Xs[nxt] + row * KVSTR + lcol * 4) = xr[it];
                *(uint4*)(Ws[nxt] + row * KVSTR + lcol * 4) = wr[it];
            }
            __syncthreads();
        }
    }

    int r0 = m0 + wm * 16 + grp;
    int r1 = r0 + 8;
    if (MODE == 0) {
        int nG = n0 + wn * 32;
        int seg = nG >> 7;
        float* dst = (seg == 0) ? g_q : (seg == 1) ? g_k : g_v;
        float sc = (seg == 0) ? QKV_SCALE : 1.0f;
        int h = (nG & 127) >> 5;
        int b0 = r0 / SEQ, nr0 = r0 - b0 * SEQ;
        int b1 = r1 / SEQ, nr1 = r1 - b1 * SEQ;
        float* d0 = dst + ((size_t)((b0 * NHEAD + h) * SEQ) + nr0) * HD + 2 * q4;
        float* d1 = dst + ((size_t)((b1 * NHEAD + h) * SEQ) + nr1) * HD + 2 * q4;
#pragma unroll
        for (int j = 0; j < 4; j++) {
            *(float2*)(d0 + j * 8) = make_float2(acc[j][0] * sc, acc[j][1] * sc);
            *(float2*)(d1 + j * 8) = make_float2(acc[j][2] * sc, acc[j][3] * sc);
        }
    } else {
        int colb = n0 + wn * 32 + 2 * q4;
        float* o0 = out + (size_t)r0 * CH + colb;
        float* o1 = out + (size_t)r1 * CH + colb;
#pragma unroll
        for (int j = 0; j < 4; j++) {
            float2 pb = *(const float2*)(bias + colb + j * 8);
            *(float2*)(o0 + j * 8) = make_float2(acc[j][0] + pb.x, acc[j][1] + pb.y);
            *(float2*)(o1 + j * 8) = make_float2(acc[j][2] + pb.x, acc[j][3] + pb.y);
        }
    }
}

// ============================================================
// Attention via mma.sync tf32: one CTA per (b,h), 8 warps,
// 2 CTAs/SM. Software-pipelined: S-mma(nt+1) issued before the
// exp/shfl/PV epilogue of tile nt, bias+mask added at exp time.
// ============================================================
#define ATTN_SMEM (2 * SEQ * KVSTR * 4)

__global__ void __launch_bounds__(256, 2) attn_mma(const float* __restrict__ mask) {
    extern __shared__ float sm[];
    float* Ks = sm;
    float* Vs = sm + SEQ * KVSTR;

    int g = blockIdx.x;
    int w = g >> 4;
    int r = g & 15;
    int b = (r >> 2) * NWIN + w;
    int h = r & 3;
    size_t base = ((size_t)(b * NHEAD + h) * SEQ) * HD;

    int tid = threadIdx.x;
    // ---- stage K/V (tf32-rounded) ----
    for (int s = tid; s < SEQ * 8; s += 256) {
        int row = s >> 3, c = s & 7;
        float4 k = *(const float4*)(g_k + base + (size_t)row * HD + c * 4);
        float4 v = *(const float4*)(g_v + base + (size_t)row * HD + c * 4);
        uint4 kt = make_uint4(f2tf32(k.x), f2tf32(k.y), f2tf32(k.z), f2tf32(k.w));
        uint4 vt = make_uint4(f2tf32(v.x), f2tf32(v.y), f2tf32(v.z), f2tf32(v.w));
        int o = row * KVSTR + c * 4;
        *(uint4*)(Ks + o) = kt;
        *(uint4*)(Vs + o) = vt;
    }
    __syncthreads();

    bool domask = (g_mflag[w] != 0);
    int lane = tid & 31, warp = tid >> 5;
    int grp = lane >> 2, q4 = lane & 3;
    int s1 = (lane & ~3) + (q4 >> 1);
    int s2 = s1 + 2;
    bool oddc = (q4 & 1);

    const float* biasp = g_bias + (size_t)h * NN;
    const float* maskp = mask + (size_t)w * NN;

    for (int mt = warp; mt < MT; mt += 8) {
        int m0 = mt * 16;
        int row0 = m0 + grp;
        int row1 = row0 + 8;
        int r1c = (row1 < SEQ) ? row1 : SEQ - 1;

        // Q fragments from gmem (reused across all 49 n-tiles)
        const float* q0p = g_q + base + (size_t)row0 * HD;
        const float* q1p = g_q + base + (size_t)r1c * HD;
        uint32_t aq[4][4];
#pragma unroll
        for (int ks = 0; ks < 4; ks++) {
            aq[ks][0] = f2tf32(q0p[ks * 8 + q4]);
            aq[ks][1] = f2tf32(q1p[ks * 8 + q4]);
            aq[ks][2] = f2tf32(q0p[ks * 8 + q4 + 4]);
            aq[ks][3] = f2tf32(q1p[ks * 8 + q4 + 4]);
        }

        const float* b0r = biasp + (size_t)row0 * SEQ + 2 * q4;
        const float* b1r = biasp + (size_t)r1c * SEQ + 2 * q4;
        const float* m0r = maskp + (size_t)row0 * SEQ + 2 * q4;
        const float* m1r = maskp + (size_t)r1c * SEQ + 2 * q4;

        float oacc[4][4] = {};
        float rs0 = 0.0f, rs1 = 0.0f;

        // ---- prologue: bm(0) and S-mma(0) (zero-init accumulator) ----
        float cc0 = 0.f, cc1 = 0.f, cc2 = 0.f, cc3 = 0.f;
        float bm0, bm1, bm2, bm3;
        {
            float2 pb0 = *(const float2*)(b0r);
            float2 pb1 = *(const float2*)(b1r);
            bm0 = pb0.x; bm1 = pb0.y; bm2 = pb1.x; bm3 = pb1.y;
            if (domask) {
                float2 pm0 = *(const float2*)(m0r);
                float2 pm1 = *(const float2*)(m1r);
                bm0 += pm0.x; bm1 += pm0.y; bm2 += pm1.x; bm3 += pm1.y;
            }
#pragma unroll
            for (int ks = 0; ks < 4; ks++) {
                const uint32_t* kp = (const uint32_t*)(Ks + grp * KVSTR + ks * 8 + q4);
                mma_tf32(cc0, cc1, cc2, cc3,
                         aq[ks][0], aq[ks][1], aq[ks][2], aq[ks][3], kp[0], kp[4]);
            }
        }

#pragma unroll 2
        for (int nt = 0; nt < NT; nt++) {
            int n0 = nt * 8;
            // ---- issue next tile's bm loads + S-mma (independent of cc) ----
            float cn0 = 0.f, cn1 = 0.f, cn2 = 0.f, cn3 = 0.f;
            float bn0 = 0.f, bn1 = 0.f, bn2 = 0.f, bn3 = 0.f;
            if (nt + 1 < NT) {
                int nn = n0 + 8;
                float2 pb0 = *(const float2*)(b0r + nn);
                float2 pb1 = *(const float2*)(b1r + nn);
                bn0 = pb0.x; bn1 = pb0.y; bn2 = pb1.x; bn3 = pb1.y;
                if (domask) {
                    float2 pm0 = *(const float2*)(m0r + nn);
                    float2 pm1 = *(const float2*)(m1r + nn);
                    bn0 += pm0.x; bn1 += pm0.y; bn2 += pm1.x; bn3 += pm1.y;
                }
#pragma unroll
                for (int ks = 0; ks < 4; ks++) {
                    const uint32_t* kp = (const uint32_t*)(Ks + (nn + grp) * KVSTR + ks * 8 + q4);
                    mma_tf32(cn0, cn1, cn2, cn3,
                             aq[ks][0], aq[ks][1], aq[ks][2], aq[ks][3], kp[0], kp[4]);
                }
            }

            // ---- epilogue of current tile ----
            float e0 = __expf(cc0 + bm0), e1 = __expf(cc1 + bm1);
            float e2 = __expf(cc2 + bm2), e3 = __expf(cc3 + bm3);
            rs0 += e0 + e1;
            rs1 += e2 + e3;

            uint32_t u0 = f2tf32(e0), u1 = f2tf32(e1);
            uint32_t u2 = f2tf32(e2), u3 = f2tf32(e3);
            uint32_t x0a = __shfl_sync(0xffffffffu, u0, s1);
            uint32_t x1a = __shfl_sync(0xffffffffu, u1, s1);
            uint32_t x2a = __shfl_sync(0xffffffffu, u2, s1);
            uint32_t x3a = __shfl_sync(0xffffffffu, u3, s1);
            uint32_t x0b = __shfl_sync(0xffffffffu, u0, s2);
            uint32_t x1b = __shfl_sync(0xffffffffu, u1, s2);
            uint32_t x2b = __shfl_sync(0xffffffffu, u2, s2);
            uint32_t x3b = __shfl_sync(0xffffffffu, u3, s2);
            uint32_t ap0 = oddc ? x1a : x0a;
            uint32_t ap1 = oddc ? x3a : x2a;
            uint32_t ap2 = oddc ? x1b : x0b;
            uint32_t ap3 = oddc ? x3b : x2b;

#pragma unroll
            for (int j = 0; j < 4; j++) {
                const uint32_t* vp0 = (const uint32_t*)(Vs + (n0 + q4) * KVSTR + j * 8 + grp);
                const uint32_t* vp1 = (const uint32_t*)(Vs + (n0 + q4 + 4) * KVSTR + j * 8 + grp);
                mma_tf32(oacc[j][0], oacc[j][1], oacc[j][2], oacc[j][3],
                         ap0, ap1, ap2, ap3, vp0[0], vp1[0]);
            }

            cc0 = cn0; cc1 = cn1; cc2 = cn2; cc3 = cn3;
            bm0 = bn0; bm1 = bn1; bm2 = bn2; bm3 = bn3;
        }

        // ---- rowsum across quad, normalize, store ----
        rs0 += __shfl_xor_sync(0xffffffffu, rs0, 1);
        rs0 += __shfl_xor_sync(0xffffffffu, rs0, 2);
        rs1 += __shfl_xor_sync(0xffffffffu, rs1, 1);
        rs1 += __shfl_xor_sync(0xffffffffu, rs1, 2);
        float inv0 = __frcp_rn(rs0), inv1 = __frcp_rn(rs1);

        {
            float* op = g_ao + ((size_t)b * SEQ + row0) * CH + h * HD + 2 * q4;
#pragma unroll
            for (int j = 0; j < 4; j++)
                *(float2*)(op + j * 8) = make_float2(oacc[j][0] * inv0, oacc[j][1] * inv0);
        }
        if (row1 < SEQ) {
            float* op = g_ao + ((size_t)b * SEQ + row1) * CH + h * HD + 2 * q4;
#pragma unroll
            for (int j = 0; j < 4; j++)
                *(float2*)(op + j * 8) = make_float2(oacc[j][2] * inv1, oacc[j][3] * inv1);
        }
    }
}

// ============================================================
extern "C" void kernel_launch(void* const* d_in, const int* in_sizes, int n_in,
                              void* d_out, int out_size) {
    (void)in_sizes; (void)n_in; (void)out_size;
    const float* x          = (const float*)d_in[0];
    const float* mask       = (const float*)d_in[1];
    const float* qkv_w      = (const float*)d_in[2];
    const float* proj_w     = (const float*)d_in[3];
    const float* proj_b     = (const float*)d_in[4];
    const float* bias_table = (const float*)d_in[5];
    const int*   rel_index  = (const int*)d_in[6];
    float* out = (float*)d_out;

    cudaFuncSetAttribute(attn_mma, cudaFuncAttributeMaxDynamicSharedMemorySize, ATTN_SMEM);

    bias_gather_kernel<<<(NN + 255) / 256, 256>>>(bias_table, rel_index);
    maskflag_kernel<<<NWIN, 256>>>(mask);
    gemm_tc<0><<<dim3(MROWS / 64, 384 / 64), 256>>>(x, qkv_w, nullptr, nullptr);
    attn_mma<<<B_TOT * NHEAD, 256, ATTN_SMEM>>>(mask);
    gemm_tc<1><<<dim3(MROWS / 64, CH / 64), 256>>>(nullptr, proj_w, proj_b, out);
}

// round 6
// speedup vs baseline: 1.6303x; 1.6303x over previous
#include <cuda_runtime.h>
#include <cuda_fp16.h>
#include <cstdint>
#include <math.h>

#define B_TOT 512
#define SEQ   392
#define CH    128
#define NHEAD 4
#define HD    32
#define NWIN  128
#define MROWS (B_TOT*SEQ)          // 200704
#define NN    (SEQ*SEQ)            // 153664
#define QKV_SCALE 0.17677669529663687f

#define MT    25                   // ceil(392/16) m-tiles
#define NT16  25                   // 24 full 16-col tiles + 1 tail (8 cols)
#define KSS   40                   // K smem stride (halves)
#define KS_ROWS 400
#define VTS   408                  // V^T smem stride (halves)
#define GSTR  136                  // gemm smem stride (halves)

// -------- scratch (device globals: no allocations allowed) --------
__device__ __half g_q[(size_t)B_TOT*NHEAD*SEQ*HD];
__device__ __half g_k[(size_t)B_TOT*NHEAD*SEQ*HD];
__device__ __half g_v[(size_t)B_TOT*NHEAD*SEQ*HD];
__device__ __half g_ao[(size_t)MROWS*CH];
__device__ __half g_bias[(size_t)NHEAD*NN];   // fp16 [h][row_q][col_k]
__device__ int    g_mflag[NWIN];

// ============================================================
__device__ __forceinline__ uint32_t pack_h2(float lo, float hi) {
    uint32_t r;
    asm("cvt.rn.f16x2.f32 %0, %1, %2;" : "=r"(r) : "f"(hi), "f"(lo));
    return r;
}
__device__ __forceinline__ void mma_f16(float& d0, float& d1, float& d2, float& d3,
                                        uint32_t a0, uint32_t a1, uint32_t a2, uint32_t a3,
                                        uint32_t b0, uint32_t b1) {
    asm volatile("mma.sync.aligned.m16n8k16.row.col.f32.f16.f16.f32 "
                 "{%0,%1,%2,%3}, {%4,%5,%6,%7}, {%8,%9}, {%0,%1,%2,%3};"
                 : "+f"(d0), "+f"(d1), "+f"(d2), "+f"(d3)
                 : "r"(a0), "r"(a1), "r"(a2), "r"(a3), "r"(b0), "r"(b1));
}

// ============================================================
// Prep: bias[h][n][m] = table[ridx[n][m]][h]  (fp16)
// ============================================================
__global__ void bias_gather_kernel(const float* __restrict__ table,
                                   const int* __restrict__ ridx) {
    int t = blockIdx.x * 256 + threadIdx.x;
    if (t >= NN) return;
    int r = ridx[t];
    float4 tv = *(const float4*)(table + (size_t)r * 4);
    g_bias[0 * (size_t)NN + t] = __float2half(tv.x);
    g_bias[1 * (size_t)NN + t] = __float2half(tv.y);
    g_bias[2 * (size_t)NN + t] = __float2half(tv.z);
    g_bias[3 * (size_t)NN + t] = __float2half(tv.w);
}

// ============================================================
// Prep: per-window "mask is nonzero" flag
// ============================================================
__global__ void maskflag_kernel(const float* __restrict__ mask) {
    int w = blockIdx.x;
    const float* mp = mask + (size_t)w * NN;
    int any = 0;
    for (int i = threadIdx.x; i < NN; i += 256)
        any |= (mp[i] != 0.0f);
    any = __syncthreads_or(any);
    if (threadIdx.x == 0) g_mflag[w] = any;
}

// ============================================================
// fp16 tensor-core GEMM: Y[M,N] = X[M,128] @ W[N,128]^T
// CTA 64x64, 8 warps (4x2), warp tile 16x32, whole K staged once.
// MODE 0: X = x (fp32), scatter fp16 into g_q (scaled) / g_k / g_v
// MODE 1: X = g_ao (fp16), Y = out (fp32) + proj_b
// ============================================================
template <int MODE>
__global__ void __launch_bounds__(256) gemm_tc(const float* __restrict__ Xf,
                                               const float* __restrict__ W,
                                               const float* __restrict__ bias,
                                               float* __restrict__ out) {
    __shared__ __half Xs[64 * GSTR];
    __shared__ __half Ws[64 * GSTR];

    int m0 = blockIdx.x * 64, n0 = blockIdx.y * 64;
    int tid = threadIdx.x, lane = tid & 31, warp = tid >> 5;
    int wm = warp >> 1, wn = warp & 1;
    int grp = lane >> 2, q4 = lane & 3;

    if (MODE == 0) {
#pragma unroll
        for (int s = tid; s < 2048; s += 256) {
            int row = s >> 5, c = s & 31;
            float4 xv = *(const float4*)(Xf + (size_t)(m0 + row) * CH + c * 4);
            uint2 p;
            p.x = pack_h2(xv.x, xv.y);
            p.y = pack_h2(xv.z, xv.w);
            *(uint2*)(Xs + row * GSTR + c * 4) = p;
        }
    } else {
#pragma unroll
        for (int s = tid; s < 1024; s += 256) {
            int row = s >> 4, c = s & 15;
            *(uint4*)(Xs + row * GSTR + c * 8) =
                *(const uint4*)(g_ao + (size_t)(m0 + row) * CH + c * 8);
        }
    }
#pragma unroll
    for (int s = tid; s < 2048; s += 256) {
        int row = s >> 5, c = s & 31;
        float4 wv = *(const float4*)(W + (size_t)(n0 + row) * CH + c * 4);
        uint2 p;
        p.x = pack_h2(wv.x, wv.y);
        p.y = pack_h2(wv.z, wv.w);
        *(uint2*)(Ws + row * GSTR + c * 4) = p;
    }
    __syncthreads();

    float acc[4][4] = {};
#pragma unroll
    for (int ks = 0; ks < 8; ks++) {
        const __half* xb = Xs + (wm * 16 + grp) * GSTR + ks * 16 + 2 * q4;
        uint32_t a0 = *(const uint32_t*)(xb);
        uint32_t a1 = *(const uint32_t*)(xb + 8 * GSTR);
        uint32_t a2 = *(const uint32_t*)(xb + 8);
        uint32_t a3 = *(const uint32_t*)(xb + 8 * GSTR + 8);
#pragma unroll
        for (int j = 0; j < 4; j++) {
            const __half* wb = Ws + (wn * 32 + j * 8 + grp) * GSTR + ks * 16 + 2 * q4;
            uint32_t b0 = *(const uint32_t*)(wb);
            uint32_t b1 = *(const uint32_t*)(wb + 8);
            mma_f16(acc[j][0], acc[j][1], acc[j][2], acc[j][3],
                    a0, a1, a2, a3, b0, b1);
        }
    }

    int r0 = m0 + wm * 16 + grp;
    int r1 = r0 + 8;
    if (MODE == 0) {
        int nG = n0 + wn * 32;
        int seg = nG >> 7;
        __half* dst = (seg == 0) ? g_q : (seg == 1) ? g_k : g_v;
        float sc = (seg == 0) ? QKV_SCALE : 1.0f;
        int h = (nG & 127) >> 5;
        int b0i = r0 / SEQ, nr0 = r0 - b0i * SEQ;
        int b1i = r1 / SEQ, nr1 = r1 - b1i * SEQ;
        __half* d0 = dst + ((size_t)((b0i * NHEAD + h) * SEQ) + nr0) * HD + 2 * q4;
        __half* d1 = dst + ((size_t)((b1i * NHEAD + h) * SEQ) + nr1) * HD + 2 * q4;
#pragma unroll
        for (int j = 0; j < 4; j++) {
            *(uint32_t*)(d0 + j * 8) = pack_h2(acc[j][0] * sc, acc[j][1] * sc);
            *(uint32_t*)(d1 + j * 8) = pack_h2(acc[j][2] * sc, acc[j][3] * sc);
        }
    } else {
        int colb = n0 + wn * 32 + 2 * q4;
        float* o0 = out + (size_t)r0 * CH + colb;
        float* o1 = out + (size_t)r1 * CH + colb;
#pragma unroll
        for (int j = 0; j < 4; j++) {
            float2 pb = *(const float2*)(bias + colb + j * 8);
            *(float2*)(o0 + j * 8) = make_float2(acc[j][0] + pb.x, acc[j][1] + pb.y);
            *(float2*)(o1 + j * 8) = make_float2(acc[j][2] + pb.x, acc[j][3] + pb.y);
        }
    }
}

// ============================================================
// fp16 attention: one CTA per (b,h), 8 warps, 3 CTAs/SM.
// K [400][40] and V^T [32][408] fp16 in smem; 16-col n-tiles;
// P relayout C-frag -> A-frag by direct f16x2 pack (no shfl).
// ============================================================
#define ATTN_SMEM (KS_ROWS*KSS*2 + HD*VTS*2)   // 58112 B

__global__ void __launch_bounds__(256, 3) attn_mma(const float* __restrict__ mask) {
    extern __shared__ __half sm[];
    __half* Ks = sm;                    // [400][40]
    __half* Vt = sm + KS_ROWS * KSS;    // [32][408]

    int g = blockIdx.x;
    int w = g >> 4;
    int r = g & 15;
    int b = (r >> 2) * NWIN + w;
    int h = r & 3;
    size_t base = ((size_t)(b * NHEAD + h) * SEQ) * HD;

    int tid = threadIdx.x;
    // ---- stage K (padded rows zeroed) ----
    const uint4 z16 = make_uint4(0, 0, 0, 0);
    for (int s = tid; s < KS_ROWS * 4; s += 256) {
        int row = s >> 2, c = s & 3;   // 8 halves per chunk
        uint4 kv = (row < SEQ) ? *(const uint4*)(g_k + base + (size_t)row * HD + c * 8) : z16;
        *(uint4*)(Ks + row * KSS + c * 8) = kv;
    }
    // ---- stage V transposed ----
    for (int s = tid; s < SEQ * 16; s += 256) {
        int row = s >> 4, dp = (s & 15) * 2;
        __half2 v2 = *(const __half2*)(g_v + base + (size_t)row * HD + dp);
        Vt[dp * VTS + row] = v2.x;
        Vt[(dp + 1) * VTS + row] = v2.y;
    }
    for (int s = tid; s < HD * 16; s += 256) {
        int d = s >> 4, c = SEQ + (s & 15);
        Vt[d * VTS + c] = __half(0.0f);
    }
    __syncthreads();

    bool domask = (g_mflag[w] != 0);
    int lane = tid & 31, warp = tid >> 5;
    int grp = lane >> 2, q4 = lane & 3;

    const __half* biasp = g_bias + (size_t)h * NN;
    const float* maskp = mask + (size_t)w * NN;

    for (int mt = warp; mt < MT; mt += 8) {
        int m0 = mt * 16;
        int row0 = m0 + grp;            // < SEQ always
        int row1 = row0 + 8;
        int r1c = (row1 < SEQ) ? row1 : SEQ - 1;

        // ---- Q A-fragments from gmem (fp16, 2 k-steps) ----
        const __half* q0p = g_q + base + (size_t)row0 * HD;
        const __half* q1p = g_q + base + (size_t)r1c * HD;
        uint32_t aq[2][4];
#pragma unroll
        for (int ks = 0; ks < 2; ks++) {
            aq[ks][0] = *(const uint32_t*)(q0p + ks * 16 + 2 * q4);
            aq[ks][1] = *(const uint32_t*)(q1p + ks * 16 + 2 * q4);
            aq[ks][2] = *(const uint32_t*)(q0p + ks * 16 + 2 * q4 + 8);
            aq[ks][3] = *(const uint32_t*)(q1p + ks * 16 + 2 * q4 + 8);
        }

        const __half* b0r = biasp + (size_t)row0 * SEQ + 2 * q4;
        const __half* b1r = biasp + (size_t)r1c * SEQ + 2 * q4;
        const float* m0r = maskp + (size_t)row0 * SEQ + 2 * q4;
        const float* m1r = maskp + (size_t)r1c * SEQ + 2 * q4;

        float oacc[4][4] = {};
        float rs0 = 0.0f, rs1 = 0.0f;

        for (int nt = 0; nt < NT16; nt++) {
            int n0 = nt * 16;
            bool tail = (nt == NT16 - 1);

            // ---- S = Q @ K^T for 16 cols (two n=8 halves) ----
            float cL0 = 0.f, cL1 = 0.f, cL2 = 0.f, cL3 = 0.f;
            float cR0 = 0.f, cR1 = 0.f, cR2 = 0.f, cR3 = 0.f;
#pragma unroll
            for (int ks = 0; ks < 2; ks++) {
                const __half* kbL = Ks + (n0 + grp) * KSS + ks * 16 + 2 * q4;
                const __half* kbR = kbL + 8 * KSS;
                uint32_t bL0 = *(const uint32_t*)(kbL);
                uint32_t bL1 = *(const uint32_t*)(kbL + 8);
                uint32_t bR0 = *(const uint32_t*)(kbR);
                uint32_t bR1 = *(const uint32_t*)(kbR + 8);
                mma_f16(cL0, cL1, cL2, cL3,
                        aq[ks][0], aq[ks][1], aq[ks][2], aq[ks][3], bL0, bL1);
                mma_f16(cR0, cR1, cR2, cR3,
                        aq[ks][0], aq[ks][1], aq[ks][2], aq[ks][3], bR0, bR1);
            }

            // ---- bias (+mask), exp ----
            float2 bL0f = __half22float2(*(const __half2*)(b0r + n0));
            float2 bL1f = __half22float2(*(const __half2*)(b1r + n0));
            if (domask) {
                float2 mm0 = *(const float2*)(m0r + n0);
                float2 mm1 = *(const float2*)(m1r + n0);
                bL0f.x += mm0.x; bL0f.y += mm0.y;
                bL1f.x += mm1.x; bL1f.y += mm1.y;
            }
            float eL0 = __expf(cL0 + bL0f.x), eL1 = __expf(cL1 + bL0f.y);
            float eL2 = __expf(cL2 + bL1f.x), eL3 = __expf(cL3 + bL1f.y);

            float eR0 = 0.f, eR1 = 0.f, eR2 = 0.f, eR3 = 0.f;
            if (!tail) {
                float2 bR0f = __half22float2(*(const __half2*)(b0r + n0 + 8));
                float2 bR1f = __half22float2(*(const __half2*)(b1r + n0 + 8));
                if (domask) {
                    float2 mm0 = *(const float2*)(m0r + n0 + 8);
                    float2 mm1 = *(const float2*)(m1r + n0 + 8);
                    bR0f.x += mm0.x; bR0f.y += mm0.y;
                    bR1f.x += mm1.x; bR1f.y += mm1.y;
                }
                eR0 = __expf(cR0 + bR0f.x); eR1 = __expf(cR1 + bR0f.y);
                eR2 = __expf(cR2 + bR1f.x); eR3 = __expf(cR3 + bR1f.y);
            }
            rs0 += (eL0 + eL1) + (eR0 + eR1);
            rs1 += (eL2 + eL3) + (eR2 + eR3);

            // ---- P: C-frag -> fp16 A-frag by direct pack ----
            uint32_t ap0 = pack_h2(eL0, eL1);
            uint32_t ap1 = pack_h2(eL2, eL3);
            uint32_t ap2 = pack_h2(eR0, eR1);
            uint32_t ap3 = pack_h2(eR2, eR3);

            // ---- O += P(16x16) @ V(16x32) ----
#pragma unroll
            for (int j = 0; j < 4; j++) {
                const __half* vb = Vt + (j * 8 + grp) * VTS + n0 + 2 * q4;
                uint32_t b0v = *(const uint32_t*)(vb);
                uint32_t b1v = *(const uint32_t*)(vb + 8);
                mma_f16(oacc[j][0], oacc[j][1], oacc[j][2], oacc[j][3],
                        ap0, ap1, ap2, ap3, b0v, b1v);
            }
        }

        // ---- rowsum across quad, normalize, store (fp16) ----
        rs0 += __shfl_xor_sync(0xffffffffu, rs0, 1);
        rs0 += __shfl_xor_sync(0xffffffffu, rs0, 2);
        rs1 += __shfl_xor_sync(0xffffffffu, rs1, 1);
        rs1 += __shfl_xor_sync(0xffffffffu, rs1, 2);
        float inv0 = __frcp_rn(rs0), inv1 = __frcp_rn(rs1);

        {
            __half* op = g_ao + ((size_t)b * SEQ + row0) * CH + h * HD + 2 * q4;
#pragma unroll
            for (int j = 0; j < 4; j++)
                *(uint32_t*)(op + j * 8) = pack_h2(oacc[j][0] * inv0, oacc[j][1] * inv0);
        }
        if (row1 < SEQ) {
            __half* op = g_ao + ((size_t)b * SEQ + row1) * CH + h * HD + 2 * q4;
#pragma unroll
            for (int j = 0; j < 4; j++)
                *(uint32_t*)(op + j * 8) = pack_h2(oacc[j][2] * inv1, oacc[j][3] * inv1);
        }
    }
}

// ============================================================
extern "C" void kernel_launch(void* const* d_in, const int* in_sizes, int n_in,
                              void* d_out, int out_size) {
    (void)in_sizes; (void)n_in; (void)out_size;
    const float* x          = (const float*)d_in[0];
    const float* mask       = (const float*)d_in[1];
    const float* qkv_w      = (const float*)d_in[2];
    const float* proj_w     = (const float*)d_in[3];
    const float* proj_b     = (const float*)d_in[4];
    const float* bias_table = (const float*)d_in[5];
    const int*   rel_index  = (const int*)d_in[6];
    float* out = (float*)d_out;

    cudaFuncSetAttribute(attn_mma, cudaFuncAttributeMaxDynamicSharedMemorySize, ATTN_SMEM);

    bias_gather_kernel<<<(NN + 255) / 256, 256>>>(bias_table, rel_index);
    maskflag_kernel<<<NWIN, 256>>>(mask);
    gemm_tc<0><<<dim3(MROWS / 64, 384 / 64), 256>>>(x, qkv_w, nullptr, nullptr);
    attn_mma<<<B_TOT * NHEAD, 256, ATTN_SMEM>>>(mask);
    gemm_tc<1><<<dim3(MROWS / 64, CH / 64), 256>>>(nullptr, proj_w, proj_b, out);
}

// round 10
// speedup vs baseline: 1.8125x; 1.1118x over previous
#include <cuda_runtime.h>
#include <cuda_fp16.h>
#include <cstdint>
#include <math.h>

#define B_TOT 512
#define SEQ   392
#define CH    128
#define NHEAD 4
#define HD    32
#define NWIN  128
#define MROWS 200704               // B_TOT*SEQ
#define NN    (SEQ*SEQ)            // 153664
#define QKV_SCALE 0.17677669529663687f
#define LOG2E 1.4426950408889634f
#define QS_LOG2E (QKV_SCALE*LOG2E)

#define MT    25                   // ceil(392/16) m-tiles
#define NT16  25                   // 24 full 16-col tiles + tail (8 cols)
#define KSS   40                   // K smem stride (halves)
#define KS_ROWS 400
#define VTS   408                  // V^T smem stride (halves)
#define GSTR  136                  // gemm smem stride (halves)
#define ONE2  0x3C003C00u

// -------- scratch (device globals: no allocations allowed) --------
__device__ __half g_xh[(size_t)MROWS*CH];
__device__ __half g_qkvwh[384*CH];
__device__ __half g_projwh[CH*CH];
__device__ __half g_q[(size_t)B_TOT*NHEAD*SEQ*HD];
__device__ __half g_k[(size_t)B_TOT*NHEAD*SEQ*HD];
__device__ __half g_v[(size_t)B_TOT*NHEAD*SEQ*HD];
__device__ __half g_ao[(size_t)MROWS*CH];
__device__ __half g_bias[(size_t)NHEAD*NN + 64];  // fp16, pre-scaled by log2e
__device__ int    g_mflag[NWIN];

// ============================================================
__device__ __forceinline__ uint32_t pack_h2(float lo, float hi) {
    uint32_t r;
    asm("cvt.rn.f16x2.f32 %0, %1, %2;" : "=r"(r) : "f"(hi), "f"(lo));
    return r;
}
__device__ __forceinline__ float ex2f(float x) {
    float y;
    asm("ex2.approx.f32 %0, %1;" : "=f"(y) : "f"(x));
    return y;
}
__device__ __forceinline__ void mma_f16(float& d0, float& d1, float& d2, float& d3,
                                        uint32_t a0, uint32_t a1, uint32_t a2, uint32_t a3,
                                        uint32_t b0, uint32_t b1) {
    asm volatile("mma.sync.aligned.m16n8k16.row.col.f32.f16.f16.f32 "
                 "{%0,%1,%2,%3}, {%4,%5,%6,%7}, {%8,%9}, {%0,%1,%2,%3};"
                 : "+f"(d0), "+f"(d1), "+f"(d2), "+f"(d3)
                 : "r"(a0), "r"(a1), "r"(a2), "r"(a3), "r"(b0), "r"(b1));
}

// ============================================================
// Prep kernels
// ============================================================
__global__ void convert_x_kernel(const float* __restrict__ x) {
    size_t t = (size_t)blockIdx.x * 256 + threadIdx.x;   // 8 elems/thread
    if (t * 8 >= (size_t)MROWS * CH) return;
    float4 a = *(const float4*)(x + t * 8);
    float4 b = *(const float4*)(x + t * 8 + 4);
    uint4 o;
    o.x = pack_h2(a.x, a.y); o.y = pack_h2(a.z, a.w);
    o.z = pack_h2(b.x, b.y); o.w = pack_h2(b.z, b.w);
    *(uint4*)(g_xh + t * 8) = o;
}
__global__ void convert_w_kernel(const float* __restrict__ qkv_w,
                                 const float* __restrict__ proj_w) {
    int t = blockIdx.x * 256 + threadIdx.x;   // 8 elems/thread
    const int QN = 384 * CH / 8;              // 6144
    const float* src; __half* dst; int i;
    if (t < QN) { src = qkv_w; dst = g_qkvwh; i = t; }
    else { src = proj_w; dst = g_projwh; i = t - QN; if (i >= CH * CH / 8) return; }
    float4 a = *(const float4*)(src + i * 8);
    float4 b = *(const float4*)(src + i * 8 + 4);
    uint4 o;
    o.x = pack_h2(a.x, a.y); o.y = pack_h2(a.z, a.w);
    o.z = pack_h2(b.x, b.y); o.w = pack_h2(b.z, b.w);
    *(uint4*)(dst + i * 8) = o;
}
__global__ void bias_gather_kernel(const float* __restrict__ table,
                                   const int* __restrict__ ridx) {
    int t = blockIdx.x * 256 + threadIdx.x;
    if (t >= NN) return;
    int r = ridx[t];
    float4 tv = *(const float4*)(table + (size_t)r * 4);
    g_bias[0 * (size_t)NN + t] = __float2half(tv.x * LOG2E);
    g_bias[1 * (size_t)NN + t] = __float2half(tv.y * LOG2E);
    g_bias[2 * (size_t)NN + t] = __float2half(tv.z * LOG2E);
    g_bias[3 * (size_t)NN + t] = __float2half(tv.w * LOG2E);
}
__global__ void maskflag_kernel(const float* __restrict__ mask) {
    int w = blockIdx.x;
    const float* mp = mask + (size_t)w * NN;
    int any = 0;
    for (int i = threadIdx.x; i < NN; i += 256)
        any |= (mp[i] != 0.0f);
    any = __syncthreads_or(any);
    if (threadIdx.x == 0) g_mflag[w] = any;
}

// ============================================================
// fp16 tensor-core GEMM: Y[M,N] = X[M,128] @ W[N,128]^T
// CTA 64x64, 8 warps (4x2), warp tile 16x32, fp16 inputs.
// Weights referenced as device globals INSIDE the kernel (fix).
// MODE 0: X = g_xh, W = g_qkvwh -> scatter g_q (scaled log2e) / g_k / g_v
// MODE 1: X = g_ao, W = g_projwh -> out (fp32) + proj_b
// ============================================================
template <int MODE>
__global__ void __launch_bounds__(256) gemm_tc(const float* __restrict__ bias,
                                               float* __restrict__ out) {
    __shared__ __half Xs[64 * GSTR];
    __shared__ __half Ws[64 * GSTR];
    const __half* X = (MODE == 0) ? g_xh : g_ao;
    const __half* W = (MODE == 0) ? g_qkvwh : g_projwh;

    int m0 = blockIdx.x * 64, n0 = blockIdx.y * 64;
    int tid = threadIdx.x, lane = tid & 31, warp = tid >> 5;
    int wm = warp >> 1, wn = warp & 1;
    int grp = lane >> 2, q4 = lane & 3;

#pragma unroll
    for (int s = tid; s < 1024; s += 256) {
        int row = s >> 4, c = s & 15;
        *(uint4*)(Xs + row * GSTR + c * 8) =
            *(const uint4*)(X + (size_t)(m0 + row) * CH + c * 8);
        *(uint4*)(Ws + row * GSTR + c * 8) =
            *(const uint4*)(W + (size_t)(n0 + row) * CH + c * 8);
    }
    __syncthreads();

    float acc[4][4] = {};
#pragma unroll
    for (int ks = 0; ks < 8; ks++) {
        const __half* xb = Xs + (wm * 16 + grp) * GSTR + ks * 16 + 2 * q4;
        uint32_t a0 = *(const uint32_t*)(xb);
        uint32_t a1 = *(const uint32_t*)(xb + 8 * GSTR);
        uint32_t a2 = *(const uint32_t*)(xb + 8);
        uint32_t a3 = *(const uint32_t*)(xb + 8 * GSTR + 8);
#pragma unroll
        for (int j = 0; j < 4; j++) {
            const __half* wb = Ws + (wn * 32 + j * 8 + grp) * GSTR + ks * 16 + 2 * q4;
            uint32_t b0 = *(const uint32_t*)(wb);
            uint32_t b1 = *(const uint32_t*)(wb + 8);
            mma_f16(acc[j][0], acc[j][1], acc[j][2], acc[j][3],
                    a0, a1, a2, a3, b0, b1);
        }
    }

    int r0 = m0 + wm * 16 + grp;
    int r1 = r0 + 8;
    if (MODE == 0) {
        int nG = n0 + wn * 32;
        int seg = nG >> 7;
        __half* dst = (seg == 0) ? g_q : (seg == 1) ? g_k : g_v;
        float sc = (seg == 0) ? (float)QS_LOG2E : 1.0f;
        int h = (nG & 127) >> 5;
        int b0i = r0 / SEQ, nr0 = r0 - b0i * SEQ;
        int b1i = r1 / SEQ, nr1 = r1 - b1i * SEQ;
        __half* d0 = dst + ((size_t)((b0i * NHEAD + h) * SEQ) + nr0) * HD + 2 * q4;
        __half* d1 = dst + ((size_t)((b1i * NHEAD + h) * SEQ) + nr1) * HD + 2 * q4;
#pragma unroll
        for (int j = 0; j < 4; j++) {
            *(uint32_t*)(d0 + j * 8) = pack_h2(acc[j][0] * sc, acc[j][1] * sc);
            *(uint32_t*)(d1 + j * 8) = pack_h2(acc[j][2] * sc, acc[j][3] * sc);
        }
    } else {
        int colb = n0 + wn * 32 + 2 * q4;
        float* o0 = out + (size_t)r0 * CH + colb;
        float* o1 = out + (size_t)r1 * CH + colb;
#pragma unroll
        for (int j = 0; j < 4; j++) {
            float2 pb = *(const float2*)(bias + colb + j * 8);
            *(float2*)(o0 + j * 8) = make_float2(acc[j][0] + pb.x, acc[j][1] + pb.y);
            *(float2*)(o1 + j * 8) = make_float2(acc[j][2] + pb.x, acc[j][3] + pb.y);
        }
    }
}

// ============================================================
// fp16 attention: scalar LDS frags (R6-validated), log2-domain
// softmax (fp32 ex2), rowsum via ones-mma.
// One CTA per (b,h), 8 warps, 3 CTAs/SM.
// ============================================================
#define ATTN_SMEM (KS_ROWS*KSS*2 + HD*VTS*2)   // 58112 B

__global__ void __launch_bounds__(256, 3) attn_mma(const float* __restrict__ mask) {
    extern __shared__ __half sm[];
    __half* Ks = sm;                    // [400][40]
    __half* Vt = sm + KS_ROWS * KSS;    // [32][408]

    int g = blockIdx.x;
    int w = g >> 4;
    int r = g & 15;
    int b = (r >> 2) * NWIN + w;
    int h = r & 3;
    size_t base = ((size_t)(b * NHEAD + h) * SEQ) * HD;

    int tid = threadIdx.x;
    const uint4 z16 = make_uint4(0, 0, 0, 0);
    for (int s = tid; s < KS_ROWS * 4; s += 256) {
        int row = s >> 2, c = s & 3;
        uint4 kv = (row < SEQ) ? *(const uint4*)(g_k + base + (size_t)row * HD + c * 8) : z16;
        *(uint4*)(Ks + row * KSS + c * 8) = kv;
    }
    for (int s = tid; s < SEQ * 16; s += 256) {
        int row = s >> 4, dp = (s & 15) * 2;
        __half2 v2 = *(const __half2*)(g_v + base + (size_t)row * HD + dp);
        Vt[dp * VTS + row] = v2.x;
        Vt[(dp + 1) * VTS + row] = v2.y;
    }
    for (int s = tid; s < HD * 16; s += 256) {
        int d = s >> 4, c = SEQ + (s & 15);
        Vt[d * VTS + c] = __half(0.0f);
    }
    __syncthreads();

    bool domask = (g_mflag[w] != 0);
    int lane = tid & 31, warp = tid >> 5;
    int grp = lane >> 2, q4 = lane & 3;

    const __half* biasp = g_bias + (size_t)h * NN;
    const float* maskp = mask + (size_t)w * NN;

    for (int mt = warp; mt < MT; mt += 8) {
        int m0 = mt * 16;
        int row0 = m0 + grp;
        int row1 = row0 + 8;
        int r1c = (row1 < SEQ) ? row1 : SEQ - 1;

        const __half* q0p = g_q + base + (size_t)row0 * HD;
        const __half* q1p = g_q + base + (size_t)r1c * HD;
        uint32_t aq[2][4];
#pragma unroll
        for (int ks = 0; ks < 2; ks++) {
            aq[ks][0] = *(const uint32_t*)(q0p + ks * 16 + 2 * q4);
            aq[ks][1] = *(const uint32_t*)(q1p + ks * 16 + 2 * q4);
            aq[ks][2] = *(const uint32_t*)(q0p + ks * 16 + 2 * q4 + 8);
            aq[ks][3] = *(const uint32_t*)(q1p + ks * 16 + 2 * q4 + 8);
        }

        const __half* b0r = biasp + (size_t)row0 * SEQ + 2 * q4;
        const __half* b1r = biasp + (size_t)r1c * SEQ + 2 * q4;
        const float* m0r = maskp + (size_t)row0 * SEQ + 2 * q4;
        const float* m1r = maskp + (size_t)r1c * SEQ + 2 * q4;

        float oacc[4][4] = {};
        float rsacc[4] = {};

        for (int nt = 0; nt < NT16; nt++) {
            int n0 = nt * 16;
            bool tail = (nt == NT16 - 1);

            // ---- S = Q @ K^T for 16 cols (scalar LDS frags) ----
            float cL0 = 0.f, cL1 = 0.f, cL2 = 0.f, cL3 = 0.f;
            float cR0 = 0.f, cR1 = 0.f, cR2 = 0.f, cR3 = 0.f;
#pragma unroll
            for (int ks = 0; ks < 2; ks++) {
                const __half* kbL = Ks + (n0 + grp) * KSS + ks * 16 + 2 * q4;
                const __half* kbR = kbL + 8 * KSS;
                uint32_t bL0 = *(const uint32_t*)(kbL);
                uint32_t bL1 = *(const uint32_t*)(kbL + 8);
                uint32_t bR0 = *(const uint32_t*)(kbR);
                uint32_t bR1 = *(const uint32_t*)(kbR + 8);
                mma_f16(cL0, cL1, cL2, cL3,
                        aq[ks][0], aq[ks][1], aq[ks][2], aq[ks][3], bL0, bL1);
                mma_f16(cR0, cR1, cR2, cR3,
                        aq[ks][0], aq[ks][1], aq[ks][2], aq[ks][3], bR0, bR1);
            }

            // ---- log2-domain bias(+mask), P = 2^(S+bias) in fp32 ----
            float2 bL0f = __half22float2(*(const __half2*)(b0r + n0));
            float2 bL1f = __half22float2(*(const __half2*)(b1r + n0));
            if (domask) {
                float2 mm0 = *(const float2*)(m0r + n0);
                float2 mm1 = *(const float2*)(m1r + n0);
                bL0f.x += mm0.x * LOG2E; bL0f.y += mm0.y * LOG2E;
                bL1f.x += mm1.x * LOG2E; bL1f.y += mm1.y * LOG2E;
            }
            float eL0 = ex2f(cL0 + bL0f.x), eL1 = ex2f(cL1 + bL0f.y);
            float eL2 = ex2f(cL2 + bL1f.x), eL3 = ex2f(cL3 + bL1f.y);

            float eR0 = 0.f, eR1 = 0.f, eR2 = 0.f, eR3 = 0.f;
            if (!tail) {
                float2 bR0f = __half22float2(*(const __half2*)(b0r + n0 + 8));
                float2 bR1f = __half22float2(*(const __half2*)(b1r + n0 + 8));
                if (domask) {
                    float2 mm0 = *(const float2*)(m0r + n0 + 8);
                    float2 mm1 = *(const float2*)(m1r + n0 + 8);
                    bR0f.x += mm0.x * LOG2E; bR0f.y += mm0.y * LOG2E;
                    bR1f.x += mm1.x * LOG2E; bR1f.y += mm1.y * LOG2E;
                }
                eR0 = ex2f(cR0 + bR0f.x); eR1 = ex2f(cR1 + bR0f.y);
                eR2 = ex2f(cR2 + bR1f.x); eR3 = ex2f(cR3 + bR1f.y);
            }

            // ---- P: C-frag -> fp16 A-frag by direct pack ----
            uint32_t ap0 = pack_h2(eL0, eL1);
            uint32_t ap1 = pack_h2(eL2, eL3);
            uint32_t ap2 = pack_h2(eR0, eR1);
            uint32_t ap3 = pack_h2(eR2, eR3);

            // ---- O += P @ V ; rowsum via ones-mma ----
#pragma unroll
            for (int j = 0; j < 4; j++) {
                const __half* vb = Vt + (j * 8 + grp) * VTS + n0 + 2 * q4;
                uint32_t b0v = *(const uint32_t*)(vb);
                uint32_t b1v = *(const uint32_t*)(vb + 8);
                mma_f16(oacc[j][0], oacc[j][1], oacc[j][2], oacc[j][3],
                        ap0, ap1, ap2, ap3, b0v, b1v);
            }
            mma_f16(rsacc[0], rsacc[1], rsacc[2], rsacc[3],
                    ap0, ap1, ap2, ap3, ONE2, ONE2);
        }

        // ---- normalize + store ----
        float inv0 = __frcp_rn(rsacc[0]);
        float inv1 = __frcp_rn(rsacc[2]);
        {
            __half* op = g_ao + ((size_t)b * SEQ + row0) * CH + h * HD + 2 * q4;
#pragma unroll
            for (int j = 0; j < 4; j++)
                *(uint32_t*)(op + j * 8) = pack_h2(oacc[j][0] * inv0, oacc[j][1] * inv0);
        }
        if (row1 < SEQ) {
            __half* op = g_ao + ((size_t)b * SEQ + row1) * CH + h * HD + 2 * q4;
#pragma unroll
            for (int j = 0; j < 4; j++)
                *(uint32_t*)(op + j * 8) = pack_h2(oacc[j][2] * inv1, oacc[j][3] * inv1);
        }
    }
}

// ============================================================
extern "C" void kernel_launch(void* const* d_in, const int* in_sizes, int n_in,
                              void* d_out, int out_size) {
    (void)in_sizes; (void)n_in; (void)out_size;
    const float* x          = (const float*)d_in[0];
    const float* mask       = (const float*)d_in[1];
    const float* qkv_w      = (const float*)d_in[2];
    const float* proj_w     = (const float*)d_in[3];
    const float* proj_b     = (const float*)d_in[4];
    const float* bias_table = (const float*)d_in[5];
    const int*   rel_index  = (const int*)d_in[6];
    float* out = (float*)d_out;

    cudaFuncSetAttribute(attn_mma, cudaFuncAttributeMaxDynamicSharedMemorySize, ATTN_SMEM);

    convert_x_kernel<<<((size_t)MROWS * CH / 8 + 255) / 256, 256>>>(x);
    convert_w_kernel<<<((384 * CH + CH * CH) / 8 + 255) / 256, 256>>>(qkv_w, proj_w);
    bias_gather_kernel<<<(NN + 255) / 256, 256>>>(bias_table, rel_index);
    maskflag_kernel<<<NWIN, 256>>>(mask);
    gemm_tc<0><<<dim3(MROWS / 64, 384 / 64), 256>>>(nullptr, nullptr);
    attn_mma<<<B_TOT * NHEAD, 256, ATTN_SMEM>>>(mask);
    gemm_tc<1><<<dim3(MROWS / 64, CH / 64), 256>>>(proj_b, out);
}

// round 11
// speedup vs baseline: 1.8800x; 1.0372x over previous
#include <cuda_runtime.h>
#include <cuda_fp16.h>
#include <cstdint>
#include <math.h>

#define B_TOT 512
#define SEQ   392
#define CH    128
#define NHEAD 4
#define HD    32
#define NWIN  128
#define MROWS 200704               // B_TOT*SEQ
#define NN    (SEQ*SEQ)            // 153664
#define QKV_SCALE 0.17677669529663687f
#define LOG2E 1.4426950408889634f
#define QS_LOG2E (QKV_SCALE*LOG2E)

#define MT    25                   // ceil(392/16) m-tiles
#define NT16  25                   // 24 full 16-col tiles + tail (8 cols)
#define KSS   40                   // K smem stride (halves)
#define KS_ROWS 400
#define VTS   408                  // V^T smem stride (halves)
#define GSTR  136                  // gemm smem stride (halves)
#define ONE2  0x3C003C00u

// -------- scratch (device globals: no allocations allowed) --------
__device__ __half g_xh[(size_t)MROWS*CH];
__device__ __half g_qkvwh[384*CH];
__device__ __half g_projwh[CH*CH];
__device__ __half g_q[(size_t)B_TOT*NHEAD*SEQ*HD];
__device__ __half g_k[(size_t)B_TOT*NHEAD*SEQ*HD];
__device__ __half g_v[(size_t)B_TOT*NHEAD*SEQ*HD];
__device__ __half g_ao[(size_t)MROWS*CH];
__device__ __half g_bias[(size_t)NHEAD*NN + 64];  // fp16, pre-scaled by log2e
__device__ int    g_mflag[NWIN];

// ============================================================
__device__ __forceinline__ uint32_t pack_h2(float lo, float hi) {
    uint32_t r;
    asm("cvt.rn.f16x2.f32 %0, %1, %2;" : "=r"(r) : "f"(hi), "f"(lo));
    return r;
}
__device__ __forceinline__ float ex2f(float x) {
    float y;
    asm("ex2.approx.f32 %0, %1;" : "=f"(y) : "f"(x));
    return y;
}
__device__ __forceinline__ uint32_t smem_u32(const void* p) {
    uint32_t a;
    asm("{ .reg .u64 t; cvta.to.shared.u64 t, %1; cvt.u32.u64 %0, t; }" : "=r"(a) : "l"(p));
    return a;
}
__device__ __forceinline__ void mma_f16(float& d0, float& d1, float& d2, float& d3,
                                        uint32_t a0, uint32_t a1, uint32_t a2, uint32_t a3,
                                        uint32_t b0, uint32_t b1) {
    asm volatile("mma.sync.aligned.m16n8k16.row.col.f32.f16.f16.f32 "
                 "{%0,%1,%2,%3}, {%4,%5,%6,%7}, {%8,%9}, {%0,%1,%2,%3};"
                 : "+f"(d0), "+f"(d1), "+f"(d2), "+f"(d3)
                 : "r"(a0), "r"(a1), "r"(a2), "r"(a3), "r"(b0), "r"(b1));
}
__device__ __forceinline__ void ldsm_x4(uint32_t& r0, uint32_t& r1, uint32_t& r2, uint32_t& r3,
                                        uint32_t addr) {
    asm volatile("ldmatrix.sync.aligned.m8n8.x4.shared.b16 {%0,%1,%2,%3}, [%4];"
                 : "=r"(r0), "=r"(r1), "=r"(r2), "=r"(r3) : "r"(addr));
}

// ============================================================
// Prep kernels
// ============================================================
__global__ void convert_x_kernel(const float* __restrict__ x) {
    size_t t = (size_t)blockIdx.x * 256 + threadIdx.x;   // 8 elems/thread
    if (t * 8 >= (size_t)MROWS * CH) return;
    float4 a = *(const float4*)(x + t * 8);
    float4 b = *(const float4*)(x + t * 8 + 4);
    uint4 o;
    o.x = pack_h2(a.x, a.y); o.y = pack_h2(a.z, a.w);
    o.z = pack_h2(b.x, b.y); o.w = pack_h2(b.z, b.w);
    *(uint4*)(g_xh + t * 8) = o;
}
__global__ void convert_w_kernel(const float* __restrict__ qkv_w,
                                 const float* __restrict__ proj_w) {
    // also zero g_mflag (runs before maskflag in the same stream)
    if (blockIdx.x == 0 && threadIdx.x < NWIN) g_mflag[threadIdx.x] = 0;
    int t = blockIdx.x * 256 + threadIdx.x;   // 8 elems/thread
    const int QN = 384 * CH / 8;              // 6144
    const float* src; __half* dst; int i;
    if (t < QN) { src = qkv_w; dst = g_qkvwh; i = t; }
    else { src = proj_w; dst = g_projwh; i = t - QN; if (i >= CH * CH / 8) return; }
    float4 a = *(const float4*)(src + i * 8);
    float4 b = *(const float4*)(src + i * 8 + 4);
    uint4 o;
    o.x = pack_h2(a.x, a.y); o.y = pack_h2(a.z, a.w);
    o.z = pack_h2(b.x, b.y); o.w = pack_h2(b.z, b.w);
    *(uint4*)(dst + i * 8) = o;
}
__global__ void bias_gather_kernel(const float* __restrict__ table,
                                   const int* __restrict__ ridx) {
    int t = blockIdx.x * 256 + threadIdx.x;
    if (t >= NN) return;
    int r = ridx[t];
    float4 tv = *(const float4*)(table + (size_t)r * 4);
    g_bias[0 * (size_t)NN + t] = __float2half(tv.x * LOG2E);
    g_bias[1 * (size_t)NN + t] = __float2half(tv.y * LOG2E);
    g_bias[2 * (size_t)NN + t] = __float2half(tv.z * LOG2E);
    g_bias[3 * (size_t)NN + t] = __float2half(tv.w * LOG2E);
}
// grid (NWIN, 8): each block scans NN/8 elements of one window
__global__ void maskflag_kernel(const float* __restrict__ mask) {
    int w = blockIdx.x;
    int slice = blockIdx.y;
    const int SL = NN / 8;                    // 19208
    const float* mp = mask + (size_t)w * NN + (size_t)slice * SL;
    int any = 0;
    for (int i = threadIdx.x; i < SL; i += 256)
        any |= (mp[i] != 0.0f);
    any = __syncthreads_or(any);
    if (threadIdx.x == 0 && any) atomicOr(&g_mflag[w], 1);
}

// ============================================================
// fp16 tensor-core GEMM: Y[M,N] = X[M,128] @ W[N,128]^T
// CTA 64x64, 8 warps (4x2), warp tile 16x32, fp16 inputs.
// Weights referenced as device globals INSIDE the kernel.
// ============================================================
template <int MODE>
__global__ void __launch_bounds__(256) gemm_tc(const float* __restrict__ bias,
                                               float* __restrict__ out) {
    __shared__ __half Xs[64 * GSTR];
    __shared__ __half Ws[64 * GSTR];
    const __half* X = (MODE == 0) ? g_xh : g_ao;
    const __half* W = (MODE == 0) ? g_qkvwh : g_projwh;

    int m0 = blockIdx.x * 64, n0 = blockIdx.y * 64;
    int tid = threadIdx.x, lane = tid & 31, warp = tid >> 5;
    int wm = warp >> 1, wn = warp & 1;
    int grp = lane >> 2, q4 = lane & 3;

#pragma unroll
    for (int s = tid; s < 1024; s += 256) {
        int row = s >> 4, c = s & 15;
        *(uint4*)(Xs + row * GSTR + c * 8) =
            *(const uint4*)(X + (size_t)(m0 + row) * CH + c * 8);
        *(uint4*)(Ws + row * GSTR + c * 8) =
            *(const uint4*)(W + (size_t)(n0 + row) * CH + c * 8);
    }
    __syncthreads();

    float acc[4][4] = {};
#pragma unroll
    for (int ks = 0; ks < 8; ks++) {
        const __half* xb = Xs + (wm * 16 + grp) * GSTR + ks * 16 + 2 * q4;
        uint32_t a0 = *(const uint32_t*)(xb);
        uint32_t a1 = *(const uint32_t*)(xb + 8 * GSTR);
        uint32_t a2 = *(const uint32_t*)(xb + 8);
        uint32_t a3 = *(const uint32_t*)(xb + 8 * GSTR + 8);
#pragma unroll
        for (int j = 0; j < 4; j++) {
            const __half* wb = Ws + (wn * 32 + j * 8 + grp) * GSTR + ks * 16 + 2 * q4;
            uint32_t b0 = *(const uint32_t*)(wb);
            uint32_t b1 = *(const uint32_t*)(wb + 8);
            mma_f16(acc[j][0], acc[j][1], acc[j][2], acc[j][3],
                    a0, a1, a2, a3, b0, b1);
        }
    }

    int r0 = m0 + wm * 16 + grp;
    int r1 = r0 + 8;
    if (MODE == 0) {
        int nG = n0 + wn * 32;
        int seg = nG >> 7;
        __half* dst = (seg == 0) ? g_q : (seg == 1) ? g_k : g_v;
        float sc = (seg == 0) ? (float)QS_LOG2E : 1.0f;
        int h = (nG & 127) >> 5;
        int b0i = r0 / SEQ, nr0 = r0 - b0i * SEQ;
        int b1i = r1 / SEQ, nr1 = r1 - b1i * SEQ;
        __half* d0 = dst + ((size_t)((b0i * NHEAD + h) * SEQ) + nr0) * HD + 2 * q4;
        __half* d1 = dst + ((size_t)((b1i * NHEAD + h) * SEQ) + nr1) * HD + 2 * q4;
#pragma unroll
        for (int j = 0; j < 4; j++) {
            *(uint32_t*)(d0 + j * 8) = pack_h2(acc[j][0] * sc, acc[j][1] * sc);
            *(uint32_t*)(d1 + j * 8) = pack_h2(acc[j][2] * sc, acc[j][3] * sc);
        }
    } else {
        int colb = n0 + wn * 32 + 2 * q4;
        float* o0 = out + (size_t)r0 * CH + colb;
        float* o1 = out + (size_t)r1 * CH + colb;
#pragma unroll
        for (int j = 0; j < 4; j++) {
            float2 pb = *(const float2*)(bias + colb + j * 8);
            *(float2*)(o0 + j * 8) = make_float2(acc[j][0] + pb.x, acc[j][1] + pb.y);
            *(float2*)(o1 + j * 8) = make_float2(acc[j][2] + pb.x, acc[j][3] + pb.y);
        }
    }
}

// ============================================================
// fp16 attention: ldmatrix frags, log2-domain softmax (fp32 ex2),
// rowsum via ones-mma. One CTA per (b,h), 8 warps, 3 CTAs/SM.
// ============================================================
#define ATTN_SMEM (KS_ROWS*KSS*2 + HD*VTS*2)   // 58112 B

__global__ void __launch_bounds__(256, 3) attn_mma(const float* __restrict__ mask) {
    extern __shared__ __half sm[];
    __half* Ks = sm;                    // [400][40]
    __half* Vt = sm + KS_ROWS * KSS;    // [32][408]

    int g = blockIdx.x;
    int w = g >> 4;
    int r = g & 15;
    int b = (r >> 2) * NWIN + w;
    int h = r & 3;
    size_t base = ((size_t)(b * NHEAD + h) * SEQ) * HD;

    int tid = threadIdx.x;
    const uint4 z16 = make_uint4(0, 0, 0, 0);
    for (int s = tid; s < KS_ROWS * 4; s += 256) {
        int row = s >> 2, c = s & 3;
        uint4 kv = (row < SEQ) ? *(const uint4*)(g_k + base + (size_t)row * HD + c * 8) : z16;
        *(uint4*)(Ks + row * KSS + c * 8) = kv;
    }
    for (int s = tid; s < SEQ * 16; s += 256) {
        int row = s >> 4, dp = (s & 15) * 2;
        __half2 v2 = *(const __half2*)(g_v + base + (size_t)row * HD + dp);
        Vt[dp * VTS + row] = v2.x;
        Vt[(dp + 1) * VTS + row] = v2.y;
    }
    for (int s = tid; s < HD * 16; s += 256) {
        int d = s >> 4, c = SEQ + (s & 15);
        Vt[d * VTS + c] = __half(0.0f);
    }
    __syncthreads();

    bool domask = (g_mflag[w] != 0);
    int lane = tid & 31, warp = tid >> 5;
    int grp = lane >> 2, q4 = lane & 3;

    // ldmatrix per-thread base addresses
    int tg = lane >> 3, tr = lane & 7;
    int rsel = (tg & 2) ? 8 : 0;
    int csel = (tg & 1) ? 8 : 0;
    uint32_t kb = smem_u32(Ks + (rsel + tr) * KSS + csel);
    uint32_t vb = smem_u32(Vt + (rsel + tr) * VTS + csel);

    const __half* biasp = g_bias + (size_t)h * NN;
    const float* maskp = mask + (size_t)w * NN;

    for (int mt = warp; mt < MT; mt += 8) {
        int m0 = mt * 16;
        int row0 = m0 + grp;
        int row1 = row0 + 8;
        int r1c = (row1 < SEQ) ? row1 : SEQ - 1;

        const __half* q0p = g_q + base + (size_t)row0 * HD;
        const __half* q1p = g_q + base + (size_t)r1c * HD;
        uint32_t aq[2][4];
#pragma unroll
        for (int ks = 0; ks < 2; ks++) {
            aq[ks][0] = *(const uint32_t*)(q0p + ks * 16 + 2 * q4);
            aq[ks][1] = *(const uint32_t*)(q1p + ks * 16 + 2 * q4);
            aq[ks][2] = *(const uint32_t*)(q0p + ks * 16 + 2 * q4 + 8);
            aq[ks][3] = *(const uint32_t*)(q1p + ks * 16 + 2 * q4 + 8);
        }

        const __half* b0r = biasp + (size_t)row0 * SEQ + 2 * q4;
        const __half* b1r = biasp + (size_t)r1c * SEQ + 2 * q4;
        const float* m0r = maskp + (size_t)row0 * SEQ + 2 * q4;
        const float* m1r = maskp + (size_t)r1c * SEQ + 2 * q4;

        float oacc[4][4] = {};
        float rsacc[4] = {};

        for (int nt = 0; nt < NT16; nt++) {
            int n0 = nt * 16;
            bool tail = (nt == NT16 - 1);

            // ---- K fragments via ldmatrix (validated mapping) ----
            uint32_t kf0[4], kf1[4];
            uint32_t kaddr = kb + (uint32_t)(n0 * (KSS * 2));
            ldsm_x4(kf0[0], kf0[1], kf0[2], kf0[3], kaddr);
            ldsm_x4(kf1[0], kf1[1], kf1[2], kf1[3], kaddr + 32);

            float cL0 = 0.f, cL1 = 0.f, cL2 = 0.f, cL3 = 0.f;
            float cR0 = 0.f, cR1 = 0.f, cR2 = 0.f, cR3 = 0.f;
            mma_f16(cL0, cL1, cL2, cL3, aq[0][0], aq[0][1], aq[0][2], aq[0][3], kf0[0], kf0[1]);
            mma_f16(cR0, cR1, cR2, cR3, aq[0][0], aq[0][1], aq[0][2], aq[0][3], kf0[2], kf0[3]);
            mma_f16(cL0, cL1, cL2, cL3, aq[1][0], aq[1][1], aq[1][2], aq[1][3], kf1[0], kf1[1]);
            mma_f16(cR0, cR1, cR2, cR3, aq[1][0], aq[1][1], aq[1][2], aq[1][3], kf1[2], kf1[3]);

            // ---- log2-domain bias(+mask), P = 2^(S+bias) in fp32 ----
            float2 bL0f = __half22float2(*(const __half2*)(b0r + n0));
            float2 bL1f = __half22float2(*(const __half2*)(b1r + n0));
            if (domask) {
                float2 mm0 = *(const float2*)(m0r + n0);
                float2 mm1 = *(const float2*)(m1r + n0);
                bL0f.x += mm0.x * LOG2E; bL0f.y += mm0.y * LOG2E;
                bL1f.x += mm1.x * LOG2E; bL1f.y += mm1.y * LOG2E;
            }
            float eL0 = ex2f(cL0 + bL0f.x), eL1 = ex2f(cL1 + bL0f.y);
            float eL2 = ex2f(cL2 + bL1f.x), eL3 = ex2f(cL3 + bL1f.y);

            float eR0 = 0.f, eR1 = 0.f, eR2 = 0.f, eR3 = 0.f;
            if (!tail) {
                float2 bR0f = __half22float2(*(const __half2*)(b0r + n0 + 8));
                float2 bR1f = __half22float2(*(const __half2*)(b1r + n0 + 8));
                if (domask) {
                    float2 mm0 = *(const float2*)(m0r + n0 + 8);
                    float2 mm1 = *(const float2*)(m1r + n0 + 8);
                    bR0f.x += mm0.x * LOG2E; bR0f.y += mm0.y * LOG2E;
                    bR1f.x += mm1.x * LOG2E; bR1f.y += mm1.y * LOG2E;
                }
                eR0 = ex2f(cR0 + bR0f.x); eR1 = ex2f(cR1 + bR0f.y);
                eR2 = ex2f(cR2 + bR1f.x); eR3 = ex2f(cR3 + bR1f.y);
            }

            uint32_t ap0 = pack_h2(eL0, eL1);
            uint32_t ap1 = pack_h2(eL2, eL3);
            uint32_t ap2 = pack_h2(eR0, eR1);
            uint32_t ap3 = pack_h2(eR2, eR3);

            // ---- V fragments via ldmatrix; O += P @ V ; ones-mma rowsum ----
            uint32_t vf0[4], vf1[4];
            uint32_t vaddr = vb + (uint32_t)(n0 * 2);
            ldsm_x4(vf0[0], vf0[1], vf0[2], vf0[3], vaddr);
            ldsm_x4(vf1[0], vf1[1], vf1[2], vf1[3], vaddr + 16 * VTS * 2);
            mma_f16(oacc[0][0], oacc[0][1], oacc[0][2], oacc[0][3], ap0, ap1, ap2, ap3, vf0[0], vf0[1]);
            mma_f16(oacc[1][0], oacc[1][1], oacc[1][2], oacc[1][3], ap0, ap1, ap2, ap3, vf0[2], vf0[3]);
            mma_f16(oacc[2][0], oacc[2][1], oacc[2][2], oacc[2][3], ap0, ap1, ap2, ap3, vf1[0], vf1[1]);
            mma_f16(oacc[3][0], oacc[3][1], oacc[3][2], oacc[3][3], ap0, ap1, ap2, ap3, vf1[2], vf1[3]);
            mma_f16(rsacc[0], rsacc[1], rsacc[2], rsacc[3], ap0, ap1, ap2, ap3, ONE2, ONE2);
        }

        // ---- normalize + store ----
        float inv0 = __frcp_rn(rsacc[0]);
        float inv1 = __frcp_rn(rsacc[2]);
        {
            __half* op = g_ao + ((size_t)b * SEQ + row0) * CH + h * HD + 2 * q4;
#pragma unroll
            for (int j = 0; j < 4; j++)
                *(uint32_t*)(op + j * 8) = pack_h2(oacc[j][0] * inv0, oacc[j][1] * inv0);
        }
        if (row1 < SEQ) {
            __half* op = g_ao + ((size_t)b * SEQ + row1) * CH + h * HD + 2 * q4;
#pragma unroll
            for (int j = 0; j < 4; j++)
                *(uint32_t*)(op + j * 8) = pack_h2(oacc[j][2] * inv1, oacc[j][3] * inv1);
        }
    }
}

// ============================================================
extern "C" void kernel_launch(void* const* d_in, const int* in_sizes, int n_in,
                              void* d_out, int out_size) {
    (void)in_sizes; (void)n_in; (void)out_size;
    const float* x          = (const float*)d_in[0];
    const float* mask       = (const float*)d_in[1];
    const float* qkv_w      = (const float*)d_in[2];
    const float* proj_w     = (const float*)d_in[3];
    const float* proj_b     = (const float*)d_in[4];
    const float* bias_table = (const float*)d_in[5];
    const int*   rel_index  = (const int*)d_in[6];
    float* out = (float*)d_out;

    cudaFuncSetAttribute(attn_mma, cudaFuncAttributeMaxDynamicSharedMemorySize, ATTN_SMEM);

    convert_x_kernel<<<((size_t)MROWS * CH / 8 + 255) / 256, 256>>>(x);
    convert_w_kernel<<<((384 * CH + CH * CH) / 8 + 255) / 256, 256>>>(qkv_w, proj_w);
    bias_gather_kernel<<<(NN + 255) / 256, 256>>>(bias_table, rel_index);
    maskflag_kernel<<<dim3(NWIN, 8), 256>>>(mask);
    gemm_tc<0><<<dim3(MROWS / 64, 384 / 64), 256>>>(nullptr, nullptr);
    attn_mma<<<B_TOT * NHEAD, 256, ATTN_SMEM>>>(mask);
    gemm_tc<1><<<dim3(MROWS / 64, CH / 64), 256>>>(proj_b, out);
}

// round 12
// speedup vs baseline: 2.1893x; 1.1645x over previous
#include <cuda_runtime.h>
#include <cuda_fp16.h>
#include <cstdint>
#include <math.h>

#define B_TOT 512
#define SEQ   392
#define CH    128
#define NHEAD 4
#define HD    32
#define NWIN  128
#define MROWS 200704               // B_TOT*SEQ
#define NN    (SEQ*SEQ)            // 153664
#define QKV_SCALE 0.17677669529663687f
#define LOG2E 1.4426950408889634f
#define QS_LOG2E (QKV_SCALE*LOG2E)

#define MT    25                   // ceil(392/16) m-tiles
#define NT16  25                   // 24 full 16-col tiles + tail (8 cols)
#define KSS   40                   // K smem stride (halves)
#define KS_ROWS 400
#define VTS   408                  // V^T smem stride (halves)
#define GSTR  136                  // gemm smem stride (halves)
#define GSMEM ((64 + 128) * GSTR * 2)   // 52224 B dynamic smem for gemm
#define ONE2  0x3C003C00u

// -------- scratch (device globals: no allocations allowed) --------
__device__ __half g_xh[(size_t)MROWS*CH];
__device__ __half g_qkvwh[384*CH];
__device__ __half g_projwh[CH*CH];
__device__ __half g_q[(size_t)B_TOT*NHEAD*SEQ*HD];
__device__ __half g_k[(size_t)B_TOT*NHEAD*SEQ*HD];
__device__ __half g_v[(size_t)B_TOT*NHEAD*SEQ*HD];
__device__ __half g_ao[(size_t)MROWS*CH];
__device__ __half g_bias[(size_t)NHEAD*NN + 64];  // fp16, pre-scaled by log2e
__device__ int    g_mflag[NWIN];

// ============================================================
__device__ __forceinline__ uint32_t pack_h2(float lo, float hi) {
    uint32_t r;
    asm("cvt.rn.f16x2.f32 %0, %1, %2;" : "=r"(r) : "f"(hi), "f"(lo));
    return r;
}
__device__ __forceinline__ float ex2f(float x) {
    float y;
    asm("ex2.approx.f32 %0, %1;" : "=f"(y) : "f"(x));
    return y;
}
__device__ __forceinline__ uint32_t smem_u32(const void* p) {
    uint32_t a;
    asm("{ .reg .u64 t; cvta.to.shared.u64 t, %1; cvt.u32.u64 %0, t; }" : "=r"(a) : "l"(p));
    return a;
}
__device__ __forceinline__ void mma_f16(float& d0, float& d1, float& d2, float& d3,
                                        uint32_t a0, uint32_t a1, uint32_t a2, uint32_t a3,
                                        uint32_t b0, uint32_t b1) {
    asm volatile("mma.sync.aligned.m16n8k16.row.col.f32.f16.f16.f32 "
                 "{%0,%1,%2,%3}, {%4,%5,%6,%7}, {%8,%9}, {%0,%1,%2,%3};"
                 : "+f"(d0), "+f"(d1), "+f"(d2), "+f"(d3)
                 : "r"(a0), "r"(a1), "r"(a2), "r"(a3), "r"(b0), "r"(b1));
}
__device__ __forceinline__ void ldsm_x4(uint32_t& r0, uint32_t& r1, uint32_t& r2, uint32_t& r3,
                                        uint32_t addr) {
    asm volatile("ldmatrix.sync.aligned.m8n8.x4.shared.b16 {%0,%1,%2,%3}, [%4];"
                 : "=r"(r0), "=r"(r1), "=r"(r2), "=r"(r3) : "r"(addr));
}

// ============================================================
// Prep kernels
// ============================================================
__global__ void convert_x_kernel(const float* __restrict__ x) {
    size_t t = (size_t)blockIdx.x * 256 + threadIdx.x;   // 8 elems/thread
    if (t * 8 >= (size_t)MROWS * CH) return;
    float4 a = *(const float4*)(x + t * 8);
    float4 b = *(const float4*)(x + t * 8 + 4);
    uint4 o;
    o.x = pack_h2(a.x, a.y); o.y = pack_h2(a.z, a.w);
    o.z = pack_h2(b.x, b.y); o.w = pack_h2(b.z, b.w);
    *(uint4*)(g_xh + t * 8) = o;
}
__global__ void convert_w_kernel(const float* __restrict__ qkv_w,
                                 const float* __restrict__ proj_w) {
    if (blockIdx.x == 0 && threadIdx.x < NWIN) g_mflag[threadIdx.x] = 0;
    int t = blockIdx.x * 256 + threadIdx.x;   // 8 elems/thread
    const int QN = 384 * CH / 8;              // 6144
    const float* src; __half* dst; int i;
    if (t < QN) { src = qkv_w; dst = g_qkvwh; i = t; }
    else { src = proj_w; dst = g_projwh; i = t - QN; if (i >= CH * CH / 8) return; }
    float4 a = *(const float4*)(src + i * 8);
    float4 b = *(const float4*)(src + i * 8 + 4);
    uint4 o;
    o.x = pack_h2(a.x, a.y); o.y = pack_h2(a.z, a.w);
    o.z = pack_h2(b.x, b.y); o.w = pack_h2(b.z, b.w);
    *(uint4*)(dst + i * 8) = o;
}
__global__ void bias_gather_kernel(const float* __restrict__ table,
                                   const int* __restrict__ ridx) {
    int t = blockIdx.x * 256 + threadIdx.x;
    if (t >= NN) return;
    int r = ridx[t];
    float4 tv = *(const float4*)(table + (size_t)r * 4);
    g_bias[0 * (size_t)NN + t] = __float2half(tv.x * LOG2E);
    g_bias[1 * (size_t)NN + t] = __float2half(tv.y * LOG2E);
    g_bias[2 * (size_t)NN + t] = __float2half(tv.z * LOG2E);
    g_bias[3 * (size_t)NN + t] = __float2half(tv.w * LOG2E);
}
__global__ void maskflag_kernel(const float* __restrict__ mask) {
    int w = blockIdx.x;
    int slice = blockIdx.y;
    const int SL = NN / 8;                    // 19208
    const float* mp = mask + (size_t)w * NN + (size_t)slice * SL;
    int any = 0;
    for (int i = threadIdx.x; i < SL; i += 256)
        any |= (mp[i] != 0.0f);
    any = __syncthreads_or(any);
    if (threadIdx.x == 0 && any) atomicOr(&g_mflag[w], 1);
}

// ============================================================
// fp16 tensor-core GEMM: Y[M,N] = X[M,128] @ W[N,128]^T
// CTA 64x128, 8 warps (4x2), warp tile 16x64, fp16 inputs,
// dynamic smem (52 KB). Halves X re-reads vs 64x64 tiles.
// MODE 0: X = g_xh, W = g_qkvwh (grid.y=3) -> g_q/g_k/g_v
// MODE 1: X = g_ao, W = g_projwh (grid.y=1) -> out + proj_b
// ============================================================
template <int MODE>
__global__ void __launch_bounds__(256) gemm_tc(const float* __restrict__ bias,
                                               float* __restrict__ out) {
    extern __shared__ __half gsm[];
    __half* Xs = gsm;               // [64][GSTR]
    __half* Ws = gsm + 64 * GSTR;   // [128][GSTR]
    const __half* X = (MODE == 0) ? g_xh : g_ao;
    const __half* W = (MODE == 0) ? g_qkvwh : g_projwh;

    int m0 = blockIdx.x * 64, n0 = blockIdx.y * 128;
    int tid = threadIdx.x, lane = tid & 31, warp = tid >> 5;
    int wm = warp >> 1, wn = warp & 1;
    int grp = lane >> 2, q4 = lane & 3;

#pragma unroll
    for (int s = tid; s < 1024; s += 256) {
        int row = s >> 4, c = s & 15;
        *(uint4*)(Xs + row * GSTR + c * 8) =
            *(const uint4*)(X + (size_t)(m0 + row) * CH + c * 8);
    }
#pragma unroll
    for (int s = tid; s < 2048; s += 256) {
        int row = s >> 4, c = s & 15;
        *(uint4*)(Ws + row * GSTR + c * 8) =
            *(const uint4*)(W + (size_t)(n0 + row) * CH + c * 8);
    }
    __syncthreads();

    float acc[8][4] = {};
#pragma unroll
    for (int ks = 0; ks < 8; ks++) {
        const __half* xb = Xs + (wm * 16 + grp) * GSTR + ks * 16 + 2 * q4;
        uint32_t a0 = *(const uint32_t*)(xb);
        uint32_t a1 = *(const uint32_t*)(xb + 8 * GSTR);
        uint32_t a2 = *(const uint32_t*)(xb + 8);
        uint32_t a3 = *(const uint32_t*)(xb + 8 * GSTR + 8);
#pragma unroll
        for (int j = 0; j < 8; j++) {
            const __half* wb = Ws + (wn * 64 + j * 8 + grp) * GSTR + ks * 16 + 2 * q4;
            uint32_t b0 = *(const uint32_t*)(wb);
            uint32_t b1 = *(const uint32_t*)(wb + 8);
            mma_f16(acc[j][0], acc[j][1], acc[j][2], acc[j][3],
                    a0, a1, a2, a3, b0, b1);
        }
    }

    int r0 = m0 + wm * 16 + grp;
    int r1 = r0 + 8;
    if (MODE == 0) {
        int nG = n0 + wn * 64;
        int b0i = r0 / SEQ, nr0 = r0 - b0i * SEQ;
        int b1i = r1 / SEQ, nr1 = r1 - b1i * SEQ;
#pragma unroll
        for (int j = 0; j < 8; j++) {
            int cG = nG + j * 8;
            int seg = cG >> 7;
            __half* dst = (seg == 0) ? g_q : (seg == 1) ? g_k : g_v;
            float sc = (seg == 0) ? (float)QS_LOG2E : 1.0f;
            int h = (cG & 127) >> 5;
            int dcol = (cG & 31) + 2 * q4;
            *(uint32_t*)(dst + ((size_t)((b0i * NHEAD + h) * SEQ) + nr0) * HD + dcol) =
                pack_h2(acc[j][0] * sc, acc[j][1] * sc);
            *(uint32_t*)(dst + ((size_t)((b1i * NHEAD + h) * SEQ) + nr1) * HD + dcol) =
                pack_h2(acc[j][2] * sc, acc[j][3] * sc);
        }
    } else {
#pragma unroll
        for (int j = 0; j < 8; j++) {
            int colb = n0 + wn * 64 + j * 8 + 2 * q4;
            float2 pb = *(const float2*)(bias + colb);
            *(float2*)(out + (size_t)r0 * CH + colb) =
                make_float2(acc[j][0] + pb.x, acc[j][1] + pb.y);
            *(float2*)(out + (size_t)r1 * CH + colb) =
                make_float2(acc[j][2] + pb.x, acc[j][3] + pb.y);
        }
    }
}

// ============================================================
// fp16 attention: ldmatrix frags, log2-domain softmax (fp32 ex2),
// ones-mma rowsum, bias prefetched one n-tile ahead.
// One CTA per (b,h), 8 warps, 3 CTAs/SM.
// ============================================================
#define ATTN_SMEM (KS_ROWS*KSS*2 + HD*VTS*2)   // 58112 B

__global__ void __launch_bounds__(256, 3) attn_mma(const float* __restrict__ mask) {
    extern __shared__ __half sm[];
    __half* Ks = sm;                    // [400][40]
    __half* Vt = sm + KS_ROWS * KSS;    // [32][408]

    int g = blockIdx.x;
    int w = g >> 4;
    int r = g & 15;
    int b = (r >> 2) * NWIN + w;
    int h = r & 3;
    size_t base = ((size_t)(b * NHEAD + h) * SEQ) * HD;

    int tid = threadIdx.x;
    const uint4 z16 = make_uint4(0, 0, 0, 0);
    for (int s = tid; s < KS_ROWS * 4; s += 256) {
        int row = s >> 2, c = s & 3;
        uint4 kv = (row < SEQ) ? *(const uint4*)(g_k + base + (size_t)row * HD + c * 8) : z16;
        *(uint4*)(Ks + row * KSS + c * 8) = kv;
    }
    for (int s = tid; s < SEQ * 16; s += 256) {
        int row = s >> 4, dp = (s & 15) * 2;
        __half2 v2 = *(const __half2*)(g_v + base + (size_t)row * HD + dp);
        Vt[dp * VTS + row] = v2.x;
        Vt[(dp + 1) * VTS + row] = v2.y;
    }
    for (int s = tid; s < HD * 16; s += 256) {
        int d = s >> 4, c = SEQ + (s & 15);
        Vt[d * VTS + c] = __half(0.0f);
    }
    __syncthreads();

    bool domask = (g_mflag[w] != 0);
    int lane = tid & 31, warp = tid >> 5;
    int grp = lane >> 2, q4 = lane & 3;

    int tg = lane >> 3, tr = lane & 7;
    int rsel = (tg & 2) ? 8 : 0;
    int csel = (tg & 1) ? 8 : 0;
    uint32_t kb = smem_u32(Ks + (rsel + tr) * KSS + csel);
    uint32_t vb = smem_u32(Vt + (rsel + tr) * VTS + csel);

    const __half* biasp = g_bias + (size_t)h * NN;
    const float* maskp = mask + (size_t)w * NN;

    for (int mt = warp; mt < MT; mt += 8) {
        int m0 = mt * 16;
        int row0 = m0 + grp;
        int row1 = row0 + 8;
        int r1c = (row1 < SEQ) ? row1 : SEQ - 1;

        const __half* q0p = g_q + base + (size_t)row0 * HD;
        const __half* q1p = g_q + base + (size_t)r1c * HD;
        uint32_t aq[2][4];
#pragma unroll
        for (int ks = 0; ks < 2; ks++) {
            aq[ks][0] = *(const uint32_t*)(q0p + ks * 16 + 2 * q4);
            aq[ks][1] = *(const uint32_t*)(q1p + ks * 16 + 2 * q4);
            aq[ks][2] = *(const uint32_t*)(q0p + ks * 16 + 2 * q4 + 8);
            aq[ks][3] = *(const uint32_t*)(q1p + ks * 16 + 2 * q4 + 8);
        }

        const __half* b0r = biasp + (size_t)row0 * SEQ + 2 * q4;
        const __half* b1r = biasp + (size_t)r1c * SEQ + 2 * q4;
        const float* m0r = maskp + (size_t)row0 * SEQ + 2 * q4;
        const float* m1r = maskp + (size_t)r1c * SEQ + 2 * q4;

        float oacc[4][4] = {};
        float rsacc[4] = {};

        // prefetch bias for nt=0
        uint32_t pb0 = *(const uint32_t*)(b0r);
        uint32_t pb1 = *(const uint32_t*)(b1r);
        uint32_t pb2 = *(const uint32_t*)(b0r + 8);
        uint32_t pb3 = *(const uint32_t*)(b1r + 8);

        for (int nt = 0; nt < NT16; nt++) {
            int n0 = nt * 16;
            bool tail = (nt == NT16 - 1);

            // ---- K fragments via ldmatrix ----
            uint32_t kf0[4], kf1[4];
            uint32_t kaddr = kb + (uint32_t)(n0 * (KSS * 2));
            ldsm_x4(kf0[0], kf0[1], kf0[2], kf0[3], kaddr);
            ldsm_x4(kf1[0], kf1[1], kf1[2], kf1[3], kaddr + 32);

            // ---- prefetch next tile's bias (one iteration of slack) ----
            uint32_t nb0 = 0, nb1 = 0, nb2 = 0, nb3 = 0;
            if (!tail) {
                int nn = n0 + 16;
                nb0 = *(const uint32_t*)(b0r + nn);
                nb1 = *(const uint32_t*)(b1r + nn);
                nb2 = *(const uint32_t*)(b0r + nn + 8);
                nb3 = *(const uint32_t*)(b1r + nn + 8);
            }

            float cL0 = 0.f, cL1 = 0.f, cL2 = 0.f, cL3 = 0.f;
            float cR0 = 0.f, cR1 = 0.f, cR2 = 0.f, cR3 = 0.f;
            mma_f16(cL0, cL1, cL2, cL3, aq[0][0], aq[0][1], aq[0][2], aq[0][3], kf0[0], kf0[1]);
            mma_f16(cR0, cR1, cR2, cR3, aq[0][0], aq[0][1], aq[0][2], aq[0][3], kf0[2], kf0[3]);
            mma_f16(cL0, cL1, cL2, cL3, aq[1][0], aq[1][1], aq[1][2], aq[1][3], kf1[0], kf1[1]);
            mma_f16(cR0, cR1, cR2, cR3, aq[1][0], aq[1][1], aq[1][2], aq[1][3], kf1[2], kf1[3]);

            // ---- log2-domain bias(+mask), P = 2^(S+bias) in fp32 ----
            float2 bL0f = __half22float2(*reinterpret_cast<__half2*>(&pb0));
            float2 bL1f = __half22float2(*reinterpret_cast<__half2*>(&pb1));
            if (domask) {
                float2 mm0 = *(const float2*)(m0r + n0);
                float2 mm1 = *(const float2*)(m1r + n0);
                bL0f.x += mm0.x * LOG2E; bL0f.y += mm0.y * LOG2E;
                bL1f.x += mm1.x * LOG2E; bL1f.y += mm1.y * LOG2E;
            }
            float eL0 = ex2f(cL0 + bL0f.x), eL1 = ex2f(cL1 + bL0f.y);
            float eL2 = ex2f(cL2 + bL1f.x), eL3 = ex2f(cL3 + bL1f.y);

            float eR0 = 0.f, eR1 = 0.f, eR2 = 0.f, eR3 = 0.f;
            if (!tail) {
                float2 bR0f = __half22float2(*reinterpret_cast<__half2*>(&pb2));
                float2 bR1f = __half22float2(*reinterpret_cast<__half2*>(&pb3));
                if (domask) {
                    float2 mm0 = *(const float2*)(m0r + n0 + 8);
                    float2 mm1 = *(const float2*)(m1r + n0 + 8);
                    bR0f.x += mm0.x * LOG2E; bR0f.y += mm0.y * LOG2E;
                    bR1f.x += mm1.x * LOG2E; bR1f.y += mm1.y * LOG2E;
                }
                eR0 = ex2f(cR0 + bR0f.x); eR1 = ex2f(cR1 + bR0f.y);
                eR2 = ex2f(cR2 + bR1f.x); eR3 = ex2f(cR3 + bR1f.y);
            }

            uint32_t ap0 = pack_h2(eL0, eL1);
            uint32_t ap1 = pack_h2(eL2, eL3);
            uint32_t ap2 = pack_h2(eR0, eR1);
            uint32_t ap3 = pack_h2(eR2, eR3);

            // ---- V fragments via ldmatrix; O += P @ V ; ones-mma rowsum ----
            uint32_t vf0[4], vf1[4];
            uint32_t vaddr = vb + (uint32_t)(n0 * 2);
            ldsm_x4(vf0[0], vf0[1], vf0[2], vf0[3], vaddr);
            ldsm_x4(vf1[0], vf1[1], vf1[2], vf1[3], vaddr + 16 * VTS * 2);
            mma_f16(oacc[0][0], oacc[0][1], oacc[0][2], oacc[0][3], ap0, ap1, ap2, ap3, vf0[0], vf0[1]);
            mma_f16(oacc[1][0], oacc[1][1], oacc[1][2], oacc[1][3], ap0, ap1, ap2, ap3, vf0[2], vf0[3]);
            mma_f16(oacc[2][0], oacc[2][1], oacc[2][2], oacc[2][3], ap0, ap1, ap2, ap3, vf1[0], vf1[1]);
            mma_f16(oacc[3][0], oacc[3][1], oacc[3][2], oacc[3][3], ap0, ap1, ap2, ap3, vf1[2], vf1[3]);
            mma_f16(rsacc[0], rsacc[1], rsacc[2], rsacc[3], ap0, ap1, ap2, ap3, ONE2, ONE2);

            pb0 = nb0; pb1 = nb1; pb2 = nb2; pb3 = nb3;
        }

        // ---- normalize + store ----
        float inv0 = __frcp_rn(rsacc[0]);
        float inv1 = __frcp_rn(rsacc[2]);
        {
            __half* op = g_ao + ((size_t)b * SEQ + row0) * CH + h * HD + 2 * q4;
#pragma unroll
            for (int j = 0; j < 4; j++)
                *(uint32_t*)(op + j * 8) = pack_h2(oacc[j][0] * inv0, oacc[j][1] * inv0);
        }
        if (row1 < SEQ) {
            __half* op = g_ao + ((size_t)b * SEQ + row1) * CH + h * HD + 2 * q4;
#pragma unroll
            for (int j = 0; j < 4; j++)
                *(uint32_t*)(op + j * 8) = pack_h2(oacc[j][2] * inv1, oacc[j][3] * inv1);
        }
    }
}

// ============================================================
extern "C" void kernel_launch(void* const* d_in, const int* in_sizes, int n_in,
                              void* d_out, int out_size) {
    (void)in_sizes; (void)n_in; (void)out_size;
    const float* x          = (const float*)d_in[0];
    const float* mask       = (const float*)d_in[1];
    const float* qkv_w      = (const float*)d_in[2];
    const float* proj_w     = (const float*)d_in[3];
    const float* proj_b     = (const float*)d_in[4];
    const float* bias_table = (const float*)d_in[5];
    const int*   rel_index  = (const int*)d_in[6];
    float* out = (float*)d_out;

    cudaFuncSetAttribute(attn_mma, cudaFuncAttributeMaxDynamicSharedMemorySize, ATTN_SMEM);
    cudaFuncSetAttribute(gemm_tc<0>, cudaFuncAttributeMaxDynamicSharedMemorySize, GSMEM);
    cudaFuncSetAttribute(gemm_tc<1>, cudaFuncAttributeMaxDynamicSharedMemorySize, GSMEM);

    convert_x_kernel<<<((size_t)MROWS * CH / 8 + 255) / 256, 256>>>(x);
    convert_w_kernel<<<((384 * CH + CH * CH) / 8 + 255) / 256, 256>>>(qkv_w, proj_w);
    bias_gather_kernel<<<(NN + 255) / 256, 256>>>(bias_table, rel_index);
    maskflag_kernel<<<dim3(NWIN, 8), 256>>>(mask);
    gemm_tc<0><<<dim3(MROWS / 64, 3), 256, GSMEM>>>(nullptr, nullptr);
    attn_mma<<<B_TOT * NHEAD, 256, ATTN_SMEM>>>(mask);
    gemm_tc<1><<<dim3(MROWS / 64, 1), 256, GSMEM>>>(proj_b, out);
}